// round 14
// baseline (speedup 1.0000x reference)
#include <cuda_runtime.h>
#include <cstdint>

typedef unsigned long long ull;

#define Bsz 1024
#define Tt 64
#define Dd 128
#define Hh 128
#define ATT 64
#define HOR 24
#define NTHR 512
#define NC7 136          // CTAs with 7 rows
#define NCTAS 148        // 136*7 + 12*6 = 1024

// ---------------- device scratch ----------------
__device__ float g_WihT[Dd * 4 * Hh];   // [k][512o]
__device__ float g_WhhT[Hh * 4 * Hh];   // [k][512o]
__device__ float g_WhhTd[Hh * 4 * Hh];  // [k][512o]
__device__ float g_hid[(size_t)Bsz * Tt * Hh];   // [b][t][h]
__device__ float g_proj[(size_t)Bsz * ATT * Tt]; // [b][a][t]

// ---------------- helpers ----------------
__device__ __forceinline__ float tanh_fast(float x) {
    float y; asm("tanh.approx.f32 %0, %1;" : "=f"(y) : "f"(x)); return y;
}
__device__ __forceinline__ float sigm(float x) { return 1.f / (1.f + __expf(-x)); }
__device__ __forceinline__ float tanh_acc(float x) {
    float ax = fabsf(x);
    float e = __expf(-2.f * ax);
    float t = (1.f - e) / (1.f + e);
    return copysignf(t, x);
}
__device__ __forceinline__ ull pack2(float lo, float hi) {
    ull r; asm("mov.b64 %0, {%1,%2};" : "=l"(r) : "f"(lo), "f"(hi)); return r;
}
__device__ __forceinline__ float2 unpack2(ull v) {
    float2 r; asm("mov.b64 {%0,%1}, %2;" : "=f"(r.x), "=f"(r.y) : "l"(v)); return r;
}
__device__ __forceinline__ void ffma2(ull &d, ull a, ull b) {
    asm("fma.rn.f32x2 %0, %1, %2, %0;" : "+l"(d) : "l"(a), "l"(b));
}
__device__ __forceinline__ void barw(int id) {  // warpgroup barrier (128 thr)
    asm volatile("bar.sync %0, 128;" :: "r"(id) : "memory");
}

// ---------------- prologue: transpose LSTM weights ----------------
__global__ void transpose_k(const float* __restrict__ Wih,
                            const float* __restrict__ Whh,
                            const float* __restrict__ Wdh) {
    int i = blockIdx.x * blockDim.x + threadIdx.x;
    if (i < 512 * 128) {
        int o = i >> 7, k = i & 127;
        g_WihT[k * 512 + o]  = Wih[i];
        g_WhhT[k * 512 + o]  = Whh[i];
        g_WhhTd[k * 512 + o] = Wdh[i];
    }
}

// smem float offsets (all multiples of 4)
#define OFF_WK     0                  // k-major attention weights [256k][64a]
#define OFF_H      16384
#define OFF_C      (OFF_H + 1024)
#define OFF_X      (OFF_C + 1024)     // context / proj staging
#define OFF_XD     (OFF_X + 1024)     // x_tilde duplicated [g][2k]
#define OFF_HD     (OFF_XD + 2048)    // h duplicated [g][2k]
#define OFF_CD     (OFF_HD + 2048)    // c duplicated [g][2k]
#define OFF_BASE   (OFF_CD + 2048)
#define OFF_SC     (OFF_BASE + 512)
#define OFF_GA     (OFF_SC + 512)     // Wih partial kh=0
#define OFF_GB     (OFF_GA + 4096)    // Whh full
#define OFF_GC     (OFF_GB + 4096)    // Wih partial kh=1
#define OFF_BIAS   (OFF_GC + 4096)
#define OFF_WEB    (OFF_BIAS + 512)
#define OFF_WV     (OFF_WEB + 64)     // (w_feat, ve_w) pairs, 128 floats
#define OFF_WDB    (OFF_WV + 128)
#define OFF_VDW    (OFF_WDB + 64)
#define OFF_DWIH   (OFF_VDW + 64)
#define OFF_FCW    (OFF_DWIH + 512)
#define OFF_YH     (OFF_FCW + 320)
#define OFF_YPREV  (OFF_YH + 512)
#define SMEM_FLOATS (OFF_YPREV + 8)
#define SMEM_BYTES  (SMEM_FLOATS * 4)

template<int GN>
__device__ __forceinline__ void darnn_body(
    const int b0,
    const float* __restrict__ X,        const float* __restrict__ y_hist,
    const float* __restrict__ We_w,     const float* __restrict__ We_b,
    const float* __restrict__ ve_w,     const float* __restrict__ ve_b,
    const float* __restrict__ enc_bih,  const float* __restrict__ enc_bhh,
    const float* __restrict__ dec_Wih,  const float* __restrict__ dec_bih,
    const float* __restrict__ dec_bhh,
    const float* __restrict__ Wd_w,     const float* __restrict__ Wd_b,
    const float* __restrict__ vd_w,     const float* __restrict__ vd_b,
    const float* __restrict__ fc_w,     const float* __restrict__ fc_b,
    float* __restrict__ out, float* sm)
{
    float* sWk     = sm + OFF_WK;
    float* s_h     = sm + OFF_H;
    float* s_c     = sm + OFF_C;
    float* s_x     = sm + OFF_X;
    float* s_xd    = sm + OFF_XD;
    float* s_hd    = sm + OFF_HD;
    float* s_cd    = sm + OFF_CD;
    float* s_base  = sm + OFF_BASE;
    float* s_sc    = sm + OFF_SC;
    float* s_gA    = sm + OFF_GA;
    float* s_gB    = sm + OFF_GB;
    float* s_gC    = sm + OFF_GC;
    float* s_bias  = sm + OFF_BIAS;
    float* s_Web   = sm + OFF_WEB;
    float* s_wv    = sm + OFF_WV;
    float* s_Wdb   = sm + OFF_WDB;
    float* s_vdw   = sm + OFF_VDW;
    float* s_dWih  = sm + OFF_DWIH;
    float* s_fcw   = sm + OFF_FCW;
    float* s_yh    = sm + OFF_YH;
    float* s_yprev = sm + OFF_YPREV;

    const int tid  = threadIdx.x;
    const int lane = tid & 31;
    const int wrp  = tid >> 5;
    const int la   = lane;
    const int gt   = tid - 256;         // gemm-warp thread id (warps 8-15)
    const int op4  = tid & 255;         // Wih-phase o-pair
    const int kh4  = tid >> 8;          // Wih-phase k-half
    const int gU   = tid >> 6;          // update: batch row
    const int i2   = (tid & 63) * 2;    // update: unit pair
    const int gg   = tid >> 7;          // proj-phase warpgroup
    const int wt   = tid & 127;
    const int g0p  = gg * 2, g1p = g0p + 1;
    const int glp  = g0p + (wt >> 6);
    const int a63  = tid & 63;
    const int WB   = 1 + gg;

    const float ve_b_r = ve_b[0];

    // ---------- preload (encoder) ----------
    for (int i = tid; i < 256 * 64; i += NTHR) {
        int k = i >> 6, a = i & 63;
        sWk[i] = We_w[a * 257 + k];       // k-major [256k][64a]
    }
    if (tid < 512) s_bias[tid] = enc_bih[tid] + enc_bhh[tid];
    if (tid < 64) {
        s_Web[tid] = We_b[tid];
        ((float2*)s_wv)[tid] = make_float2(We_w[tid * 257 + 256], ve_w[tid]);
    }
    if (tid < GN * Tt) s_yh[tid] = y_hist[b0 * Tt + tid];
    for (int i = tid; i < 1024; i += NTHR) { s_h[i] = 0.f; s_c[i] = 0.f; }
    for (int i = tid; i < 2048; i += NTHR) { s_hd[i] = 0.f; s_cd[i] = 0.f; }
    __syncthreads();

    const ull* WihP  = reinterpret_cast<const ull*>(g_WihT);   // [k][256 o-pairs]
    const ull* WhhP  = reinterpret_cast<const ull*>(g_WhhT);
    const ull* WhhPd = reinterpret_cast<const ull*>(g_WhhTd);

    // ================= ENCODER: 64 steps =================
    for (int t = 0; t < Tt; ++t) {
        if (wrp < GN) {
            const int r = wrp;   // batch row
            // ---- E2: base, lane computes a-pair (2la, 2la+1); k-major weights ----
            {
                const ull* Wk = (const ull*)sWk;   // [k][32 ull]
                const ulonglong2* hd2 = (const ulonglong2*)(s_hd + r * 256);
                const ulonglong2* cd2 = (const ulonglong2*)(s_cd + r * 256);
                ull aA = pack2(s_Web[2 * la], s_Web[2 * la + 1]), aB = 0ULL;
                #pragma unroll 8
                for (int kp = 0; kp < 64; ++kp) {
                    ulonglong2 hp = hd2[kp];
                    ffma2(aA, Wk[(2 * kp) * 32 + la], hp.x);
                    ffma2(aB, Wk[(2 * kp + 1) * 32 + la], hp.y);
                }
                #pragma unroll 8
                for (int kp = 0; kp < 64; ++kp) {
                    ulonglong2 cp = cd2[kp];
                    ffma2(aA, Wk[(128 + 2 * kp) * 32 + la], cp.x);
                    ffma2(aB, Wk[(129 + 2 * kp) * 32 + la], cp.y);
                }
                float2 ra = unpack2(aA), rb = unpack2(aB);
                *(float2*)(s_base + r * 64 + 2 * la) = make_float2(ra.x + rb.x, ra.y + rb.y);
            }
            __syncwarp();
            // ---- E3+E4: scores + softmax (warp) + x_tilde ----
            {
                const float* Xg = X + ((size_t)(b0 + r) * Tt + t) * Dd;
                float xv0 = Xg[la], xv1 = Xg[la + 32], xv2 = Xg[la + 64], xv3 = Xg[la + 96];
                float s0 = ve_b_r, s1 = ve_b_r, s2 = ve_b_r, s3 = ve_b_r;
                const float* bg = s_base + r * 64;
                const float2* wv = (const float2*)s_wv;
                #pragma unroll 8
                for (int a = 0; a < 64; ++a) {
                    float ba = bg[a];
                    float2 w = wv[a];   // (w_feat, ve_w)
                    s0 = fmaf(w.y, tanh_fast(fmaf(xv0, w.x, ba)), s0);
                    s1 = fmaf(w.y, tanh_fast(fmaf(xv1, w.x, ba)), s1);
                    s2 = fmaf(w.y, tanh_fast(fmaf(xv2, w.x, ba)), s2);
                    s3 = fmaf(w.y, tanh_fast(fmaf(xv3, w.x, ba)), s3);
                }
                float m = fmaxf(fmaxf(s0, s1), fmaxf(s2, s3));
                #pragma unroll
                for (int o = 16; o; o >>= 1) m = fmaxf(m, __shfl_xor_sync(0xffffffffu, m, o));
                float e0 = __expf(s0 - m), e1 = __expf(s1 - m);
                float e2 = __expf(s2 - m), e3 = __expf(s3 - m);
                float ss = (e0 + e1) + (e2 + e3);
                #pragma unroll
                for (int o = 16; o; o >>= 1) ss += __shfl_xor_sync(0xffffffffu, ss, o);
                float inv = 1.f / ss;
                float v0 = xv0 * e0 * inv, v1 = xv1 * e1 * inv;
                float v2 = xv2 * e2 * inv, v3 = xv3 * e3 * inv;
                float* xd = s_xd + r * 256;
                *(float2*)(xd + 2 * la)        = make_float2(v0, v0);
                *(float2*)(xd + 2 * la + 64)   = make_float2(v1, v1);
                *(float2*)(xd + 2 * la + 128)  = make_float2(v2, v2);
                *(float2*)(xd + 2 * la + 192)  = make_float2(v3, v3);
            }
        } else if (wrp >= 8) {
            // ---- Whh · h -> s_gB (full k=128), 256 threads, op = gt ----
            ull acc[GN];
            #pragma unroll
            for (int g = 0; g < GN; ++g) acc[g] = 0ULL;
            #pragma unroll 2
            for (int kp = 0; kp < 64; ++kp) {
                ull w0 = WhhP[(2 * kp) * 256 + gt];
                ull w1 = WhhP[(2 * kp + 1) * 256 + gt];
                #pragma unroll
                for (int g = 0; g < GN; ++g) {
                    ulonglong2 hp = *(const ulonglong2*)(s_hd + g * 256 + 4 * kp);
                    ffma2(acc[g], w0, hp.x);
                    ffma2(acc[g], w1, hp.y);
                }
            }
            #pragma unroll
            for (int g = 0; g < GN; ++g) {
                float2 r2 = unpack2(acc[g]);
                *(float2*)(s_gB + g * 512 + 2 * gt) = r2;
            }
        }
        __syncthreads();
        // ---- phase4: Wih · x_tilde, (op4, kh4) split ----
        {
            float* dst = kh4 ? s_gC : s_gA;
            const int kb = kh4 * 64;
            ull acc[GN];
            #pragma unroll
            for (int g = 0; g < GN; ++g) acc[g] = 0ULL;
            #pragma unroll 2
            for (int kp = 0; kp < 32; ++kp) {
                int k = kb + 2 * kp;
                ull w0 = WihP[k * 256 + op4];
                ull w1 = WihP[(k + 1) * 256 + op4];
                #pragma unroll
                for (int g = 0; g < GN; ++g) {
                    ulonglong2 xp = *(const ulonglong2*)(s_xd + g * 256 + 2 * k);
                    ffma2(acc[g], w0, xp.x);
                    ffma2(acc[g], w1, xp.y);
                }
            }
            #pragma unroll
            for (int g = 0; g < GN; ++g) {
                float2 r2 = unpack2(acc[g]);
                *(float2*)(dst + g * 512 + 2 * op4) = r2;
            }
        }
        __syncthreads();
        // ---- E6: LSTM update, 2 units per thread ----
        if (gU < GN) {
            const float2* gA2 = (const float2*)(s_gA + gU * 512);
            const float2* gB2 = (const float2*)(s_gB + gU * 512);
            const float2* gC2 = (const float2*)(s_gC + gU * 512);
            const float2* b2  = (const float2*)s_bias;
            const int h2i = i2 >> 1;
            float pre[4][2];
            #pragma unroll
            for (int q = 0; q < 4; ++q) {
                int idx = q * 64 + h2i;
                float2 vA = gA2[idx], vB = gB2[idx], vC = gC2[idx], vb = b2[idx];
                pre[q][0] = ((vA.x + vB.x) + (vC.x + vb.x));
                pre[q][1] = ((vA.y + vB.y) + (vC.y + vb.y));
            }
            float hh[2], cc[2];
            #pragma unroll
            for (int j = 0; j < 2; ++j) {
                float ig = sigm(pre[0][j]);
                float fg = sigm(pre[1][j]);
                float gv = tanh_acc(pre[2][j]);
                float og = sigm(pre[3][j]);
                cc[j] = fmaf(fg, s_c[gU * 128 + i2 + j], ig * gv);
                hh[j] = og * tanh_acc(cc[j]);
                s_c[gU * 128 + i2 + j] = cc[j];
                s_h[gU * 128 + i2 + j] = hh[j];
            }
            *(float4*)(s_hd + gU * 256 + 2 * i2) = make_float4(hh[0], hh[0], hh[1], hh[1]);
            *(float4*)(s_cd + gU * 256 + 2 * i2) = make_float4(cc[0], cc[0], cc[1], cc[1]);
            *(float2*)(g_hid + ((size_t)(b0 + gU) * Tt + t) * Hh + i2) = make_float2(hh[0], hh[1]);
        }
        __syncthreads();
    }

    // ================= enc_proj (k-major weights in sWk) =================
    for (int i = tid; i < 128 * 64; i += NTHR) {
        int k = i >> 6, a = i & 63;
        sWk[i] = Wd_w[a * 384 + k];
    }
    __syncthreads();
    for (int t = 0; t < Tt; ++t) {
        if (g0p < GN) s_x[g0p * 128 + wt] = g_hid[((size_t)(b0 + g0p) * Tt + t) * Hh + wt];
        if (g1p < GN) s_x[g1p * 128 + wt] = g_hid[((size_t)(b0 + g1p) * Tt + t) * Hh + wt];
        barw(WB);
        if (glp < GN) {
            const float* hb = s_x + glp * 128;
            float aA = 0.f, aB = 0.f;
            #pragma unroll 8
            for (int k = 0; k < 128; k += 2) {
                aA = fmaf(hb[k],     sWk[k * 64 + a63], aA);
                aB = fmaf(hb[k + 1], sWk[(k + 1) * 64 + a63], aB);
            }
            g_proj[((size_t)(b0 + glp)) * ATT * Tt + a63 * Tt + t] = aA + aB;
        }
        barw(WB);
    }

    // ---------- preload (decoder) ----------
    __syncthreads();
    for (int i = tid; i < 256 * 64; i += NTHR) {
        int k = i >> 6, a = i & 63;
        sWk[i] = Wd_w[a * 384 + 128 + k];   // [d-part; c-part] k-major
    }
    if (tid < 512) {
        s_bias[tid] = dec_bih[tid] + dec_bhh[tid];
        s_dWih[tid] = dec_Wih[tid];
    }
    if (tid < 64) { s_Wdb[tid] = Wd_b[tid]; s_vdw[tid] = vd_w[tid]; }
    if (tid < 320) s_fcw[tid] = fc_w[tid];
    for (int i = tid; i < 1024; i += NTHR) { s_h[i] = 0.f; s_c[i] = 0.f; }
    for (int i = tid; i < 2048; i += NTHR) { s_hd[i] = 0.f; s_cd[i] = 0.f; }
    if (tid < GN) s_yprev[tid] = s_yh[tid * Tt + Tt - 1];
    const float vd_b_r = vd_b[0];
    const float fc_b_r = fc_b[0];
    __syncthreads();

    // D7 helper
    auto do_D7 = [&](int s) {
        const int r = wrp;
        float acc = 0.f;
        #pragma unroll
        for (int it = 0; it < 10; ++it) {
            int idx = lane + it * 32;
            float v;
            if (idx < 128)      v = s_h[r * 128 + idx];
            else if (idx < 256) v = s_x[r * 128 + idx - 128];
            else                v = s_yh[r * 64 + idx - 256];
            acc = fmaf(s_fcw[idx], v, acc);
        }
        #pragma unroll
        for (int o = 16; o; o >>= 1) acc += __shfl_xor_sync(0xffffffffu, acc, o);
        if (lane == 0) {
            float ov = acc + fc_b_r;
            s_yprev[r] = ov;
            out[(b0 + r) * HOR + s] = ov;
        }
    };

    // ================= DECODER: 24 steps =================
    for (int s = 0; s < HOR; ++s) {
        if (wrp < GN) {
            const int r = wrp;
            if (s > 0) do_D7(s - 1);
            // ---- D1: dc, lane computes a-pair (2la,2la+1); k-major weights ----
            {
                const ull* Wk = (const ull*)sWk;
                const ulonglong2* dd2 = (const ulonglong2*)(s_hd + r * 256);
                const ulonglong2* cd2 = (const ulonglong2*)(s_cd + r * 256);
                ull aA = pack2(s_Wdb[2 * la], s_Wdb[2 * la + 1]), aB = 0ULL;
                #pragma unroll 8
                for (int kp = 0; kp < 64; ++kp) {
                    ulonglong2 dp = dd2[kp];
                    ffma2(aA, Wk[(2 * kp) * 32 + la], dp.x);
                    ffma2(aB, Wk[(2 * kp + 1) * 32 + la], dp.y);
                }
                #pragma unroll 8
                for (int kp = 0; kp < 64; ++kp) {
                    ulonglong2 cp = cd2[kp];
                    ffma2(aA, Wk[(128 + 2 * kp) * 32 + la], cp.x);
                    ffma2(aB, Wk[(129 + 2 * kp) * 32 + la], cp.y);
                }
                float2 ra = unpack2(aA), rb = unpack2(aB);
                *(float2*)(s_base + r * 64 + 2 * la) = make_float2(ra.x + rb.x, ra.y + rb.y);
            }
            __syncwarp();
            // ---- D2+D3: temporal scores + softmax (warp) -> beta ----
            {
                const float* pp = g_proj + ((size_t)(b0 + r)) * ATT * Tt;
                const float* bg = s_base + r * 64;
                float ac0 = vd_b_r, ac1 = vd_b_r;
                #pragma unroll 4
                for (int a = 0; a < 64; ++a) {
                    float dca = bg[a];
                    float vw = s_vdw[a];
                    float p0 = pp[a * 64 + la];
                    float p1 = pp[a * 64 + la + 32];
                    ac0 = fmaf(vw, tanh_fast(p0 + dca), ac0);
                    ac1 = fmaf(vw, tanh_fast(p1 + dca), ac1);
                }
                float m = fmaxf(ac0, ac1);
                #pragma unroll
                for (int o = 16; o; o >>= 1) m = fmaxf(m, __shfl_xor_sync(0xffffffffu, m, o));
                float e0 = __expf(ac0 - m), e1 = __expf(ac1 - m);
                float ss = e0 + e1;
                #pragma unroll
                for (int o = 16; o; o >>= 1) ss += __shfl_xor_sync(0xffffffffu, ss, o);
                float inv = 1.f / ss;
                s_sc[r * 64 + la]      = e0 * inv;
                s_sc[r * 64 + la + 32] = e1 * inv;
            }
            __syncwarp();
            // ---- D4: context -> s_x (4 units per lane, float4) ----
            {
                const int u4 = 4 * la;
                const float4* hp4 = (const float4*)(g_hid + ((size_t)(b0 + r) * Tt) * Hh + u4);
                const float* be = s_sc + r * 64;
                float4 acc = make_float4(0.f, 0.f, 0.f, 0.f);
                #pragma unroll 4
                for (int tt = 0; tt < 64; ++tt) {
                    float b = be[tt];
                    float4 hv = hp4[tt * 32];
                    acc.x = fmaf(b, hv.x, acc.x);
                    acc.y = fmaf(b, hv.y, acc.y);
                    acc.z = fmaf(b, hv.z, acc.z);
                    acc.w = fmaf(b, hv.w, acc.w);
                }
                *(float4*)(s_x + r * 128 + u4) = acc;
            }
        } else if (wrp >= 8) {
            // ---- D5: Whh_dec · h -> s_gB (full k=128) ----
            ull acc[GN];
            #pragma unroll
            for (int g = 0; g < GN; ++g) acc[g] = 0ULL;
            #pragma unroll 2
            for (int kp = 0; kp < 64; ++kp) {
                ull w0 = WhhPd[(2 * kp) * 256 + gt];
                ull w1 = WhhPd[(2 * kp + 1) * 256 + gt];
                #pragma unroll
                for (int g = 0; g < GN; ++g) {
                    ulonglong2 hp = *(const ulonglong2*)(s_hd + g * 256 + 4 * kp);
                    ffma2(acc[g], w0, hp.x);
                    ffma2(acc[g], w1, hp.y);
                }
            }
            #pragma unroll
            for (int g = 0; g < GN; ++g) {
                float2 r2 = unpack2(acc[g]);
                *(float2*)(s_gB + g * 512 + 2 * gt) = r2;
            }
        }
        __syncthreads();
        // ---- D6: LSTM update (gB + bias + dWih*y_prev) ----
        if (gU < GN) {
            const float2* gB2 = (const float2*)(s_gB + gU * 512);
            const float2* b2  = (const float2*)s_bias;
            const float2* w2p = (const float2*)s_dWih;
            const int h2i = i2 >> 1;
            float y = s_yprev[gU];
            float pre[4][2];
            #pragma unroll
            for (int q = 0; q < 4; ++q) {
                int idx = q * 64 + h2i;
                float2 vB = gB2[idx], vb = b2[idx], vw = w2p[idx];
                pre[q][0] = fmaf(vw.x, y, vB.x + vb.x);
                pre[q][1] = fmaf(vw.y, y, vB.y + vb.y);
            }
            float hh[2], cc[2];
            #pragma unroll
            for (int j = 0; j < 2; ++j) {
                float ig = sigm(pre[0][j]);
                float fg = sigm(pre[1][j]);
                float gv = tanh_acc(pre[2][j]);
                float og = sigm(pre[3][j]);
                cc[j] = fmaf(fg, s_c[gU * 128 + i2 + j], ig * gv);
                hh[j] = og * tanh_acc(cc[j]);
                s_c[gU * 128 + i2 + j] = cc[j];
                s_h[gU * 128 + i2 + j] = hh[j];
            }
            *(float4*)(s_hd + gU * 256 + 2 * i2) = make_float4(hh[0], hh[0], hh[1], hh[1]);
            *(float4*)(s_cd + gU * 256 + 2 * i2) = make_float4(cc[0], cc[0], cc[1], cc[1]);
        }
        __syncthreads();
    }
    // final output step
    if (wrp < GN) do_D7(HOR - 1);
}

__global__ void __launch_bounds__(NTHR, 1)
darnn_kernel(const float* __restrict__ X,        const float* __restrict__ y_hist,
             const float* __restrict__ We_w,     const float* __restrict__ We_b,
             const float* __restrict__ ve_w,     const float* __restrict__ ve_b,
             const float* __restrict__ enc_bih,  const float* __restrict__ enc_bhh,
             const float* __restrict__ dec_Wih,  const float* __restrict__ dec_bih,
             const float* __restrict__ dec_bhh,
             const float* __restrict__ Wd_w,     const float* __restrict__ Wd_b,
             const float* __restrict__ vd_w,     const float* __restrict__ vd_b,
             const float* __restrict__ fc_w,     const float* __restrict__ fc_b,
             float* __restrict__ out) {
    extern __shared__ float sm[];
    if (blockIdx.x < NC7) {
        darnn_body<7>(blockIdx.x * 7,
                      X, y_hist, We_w, We_b, ve_w, ve_b, enc_bih, enc_bhh,
                      dec_Wih, dec_bih, dec_bhh, Wd_w, Wd_b, vd_w, vd_b,
                      fc_w, fc_b, out, sm);
    } else {
        darnn_body<6>(NC7 * 7 + (blockIdx.x - NC7) * 6,
                      X, y_hist, We_w, We_b, ve_w, ve_b, enc_bih, enc_bhh,
                      dec_Wih, dec_bih, dec_bhh, Wd_w, Wd_b, vd_w, vd_b,
                      fc_w, fc_b, out, sm);
    }
}

extern "C" void kernel_launch(void* const* d_in, const int* in_sizes, int n_in,
                              void* d_out, int out_size) {
    const float* X        = (const float*)d_in[0];
    const float* y_hist   = (const float*)d_in[1];
    const float* We_w     = (const float*)d_in[2];
    const float* We_b     = (const float*)d_in[3];
    const float* ve_w     = (const float*)d_in[4];
    const float* ve_b     = (const float*)d_in[5];
    const float* enc_Wih  = (const float*)d_in[6];
    const float* enc_Whh  = (const float*)d_in[7];
    const float* enc_bih  = (const float*)d_in[8];
    const float* enc_bhh  = (const float*)d_in[9];
    const float* dec_Wih  = (const float*)d_in[10];
    const float* dec_Whh  = (const float*)d_in[11];
    const float* dec_bih  = (const float*)d_in[12];
    const float* dec_bhh  = (const float*)d_in[13];
    const float* Wd_w     = (const float*)d_in[14];
    const float* Wd_b     = (const float*)d_in[15];
    const float* vd_w     = (const float*)d_in[16];
    const float* vd_b     = (const float*)d_in[17];
    const float* fc_w     = (const float*)d_in[18];
    const float* fc_b     = (const float*)d_in[19];
    float* out = (float*)d_out;

    cudaFuncSetAttribute(darnn_kernel,
                         cudaFuncAttributeMaxDynamicSharedMemorySize, SMEM_BYTES);

    transpose_k<<<(512 * 128 + 255) / 256, 256>>>(enc_Wih, enc_Whh, dec_Whh);
    darnn_kernel<<<NCTAS, NTHR, SMEM_BYTES>>>(
        X, y_hist, We_w, We_b, ve_w, ve_b,
        enc_bih, enc_bhh, dec_Wih, dec_bih, dec_bhh,
        Wd_w, Wd_b, vd_w, vd_b, fc_w, fc_b, out);
}

// round 15
// speedup vs baseline: 1.0055x; 1.0055x over previous
#include <cuda_runtime.h>
#include <cstdint>

typedef unsigned long long ull;

#define Bsz 1024
#define Tt 64
#define Dd 128
#define Hh 128
#define ATT 64
#define HOR 24
#define NTHR 512
#define NC7 136          // CTAs with 7 rows
#define NCTAS 148        // 136*7 + 12*6 = 1024

// ---------------- device scratch ----------------
__device__ float g_WihT[Dd * 4 * Hh];   // [k][512o]
__device__ float g_WhhT[Hh * 4 * Hh];   // [k][512o]
__device__ float g_WhhTd[Hh * 4 * Hh];  // [k][512o]
__device__ float g_hid[(size_t)Bsz * Tt * Hh];   // [b][t][h]
__device__ float g_proj[(size_t)Bsz * ATT * Tt]; // [b][a][t]

// ---------------- helpers ----------------
__device__ __forceinline__ float tanh_fast(float x) {
    float y; asm("tanh.approx.f32 %0, %1;" : "=f"(y) : "f"(x)); return y;
}
__device__ __forceinline__ float sigm(float x) { return 1.f / (1.f + __expf(-x)); }
__device__ __forceinline__ float tanh_acc(float x) {
    float ax = fabsf(x);
    float e = __expf(-2.f * ax);
    float t = (1.f - e) / (1.f + e);
    return copysignf(t, x);
}
__device__ __forceinline__ ull pack2(float lo, float hi) {
    ull r; asm("mov.b64 %0, {%1,%2};" : "=l"(r) : "f"(lo), "f"(hi)); return r;
}
__device__ __forceinline__ float2 unpack2(ull v) {
    float2 r; asm("mov.b64 {%0,%1}, %2;" : "=f"(r.x), "=f"(r.y) : "l"(v)); return r;
}
__device__ __forceinline__ void ffma2(ull &d, ull a, ull b) {
    asm("fma.rn.f32x2 %0, %1, %2, %0;" : "+l"(d) : "l"(a), "l"(b));
}
__device__ __forceinline__ void barw(int id) {  // warpgroup barrier (128 thr)
    asm volatile("bar.sync %0, 128;" :: "r"(id) : "memory");
}
__device__ __forceinline__ void bar8(int cnt) { // att-warp barrier
    asm volatile("bar.sync 8, %0;" :: "r"(cnt) : "memory");
}

// ---------------- prologue: transpose LSTM weights ----------------
__global__ void transpose_k(const float* __restrict__ Wih,
                            const float* __restrict__ Whh,
                            const float* __restrict__ Wdh) {
    int i = blockIdx.x * blockDim.x + threadIdx.x;
    if (i < 512 * 128) {
        int o = i >> 7, k = i & 127;
        g_WihT[k * 512 + o]  = Wih[i];
        g_WhhT[k * 512 + o]  = Whh[i];
        g_WhhTd[k * 512 + o] = Wdh[i];
    }
}

// smem float offsets (all multiples of 4)
#define OFF_WK     0                  // k-major attention weights [256k][64a]
#define OFF_H      16384
#define OFF_C      (OFF_H + 1024)
#define OFF_X      (OFF_C + 1024)     // context / proj staging
#define OFF_XD     (OFF_X + 1024)     // x_tilde duplicated [g][2k]
#define OFF_HD     (OFF_XD + 2048)    // h duplicated [g][2k]
#define OFF_CD     (OFF_HD + 2048)    // c duplicated [g][2k]
#define OFF_BASE   (OFF_CD + 2048)
#define OFF_SC     (OFF_BASE + 512)
#define OFF_GA     (OFF_SC + 512)     // Wih partial kh=0 (reused as E2/D1 partials)
#define OFF_GB     (OFF_GA + 4096)    // Whh full
#define OFF_GC     (OFF_GB + 4096)    // Wih partial kh=1
#define OFF_BIAS   (OFF_GC + 4096)
#define OFF_WEB    (OFF_BIAS + 512)
#define OFF_WV     (OFF_WEB + 64)     // (w_feat, ve_w) pairs, 128 floats
#define OFF_WDB    (OFF_WV + 128)
#define OFF_VDW    (OFF_WDB + 64)
#define OFF_DWIH   (OFF_VDW + 64)
#define OFF_FCW    (OFF_DWIH + 512)
#define OFF_YH     (OFF_FCW + 320)
#define OFF_YPREV  (OFF_YH + 512)
#define SMEM_FLOATS (OFF_YPREV + 8)
#define SMEM_BYTES  (SMEM_FLOATS * 4)

template<int GN>
__device__ __forceinline__ void darnn_body(
    const int b0,
    const float* __restrict__ X,        const float* __restrict__ y_hist,
    const float* __restrict__ We_w,     const float* __restrict__ We_b,
    const float* __restrict__ ve_w,     const float* __restrict__ ve_b,
    const float* __restrict__ enc_bih,  const float* __restrict__ enc_bhh,
    const float* __restrict__ dec_Wih,  const float* __restrict__ dec_bih,
    const float* __restrict__ dec_bhh,
    const float* __restrict__ Wd_w,     const float* __restrict__ Wd_b,
    const float* __restrict__ vd_w,     const float* __restrict__ vd_b,
    const float* __restrict__ fc_w,     const float* __restrict__ fc_b,
    float* __restrict__ out, float* sm)
{
    constexpr int KPC = 64 / GN;        // k-pair chunk per att warp

    float* sWk     = sm + OFF_WK;
    float* s_h     = sm + OFF_H;
    float* s_c     = sm + OFF_C;
    float* s_x     = sm + OFF_X;
    float* s_xd    = sm + OFF_XD;
    float* s_hd    = sm + OFF_HD;
    float* s_cd    = sm + OFF_CD;
    float* s_base  = sm + OFF_BASE;
    float* s_sc    = sm + OFF_SC;
    float* s_gA    = sm + OFF_GA;
    float* s_gB    = sm + OFF_GB;
    float* s_gC    = sm + OFF_GC;
    float* s_ep    = s_gA;              // E2/D1 partials live in gA during phase1
    float* s_bias  = sm + OFF_BIAS;
    float* s_Web   = sm + OFF_WEB;
    float* s_wv    = sm + OFF_WV;
    float* s_Wdb   = sm + OFF_WDB;
    float* s_vdw   = sm + OFF_VDW;
    float* s_dWih  = sm + OFF_DWIH;
    float* s_fcw   = sm + OFF_FCW;
    float* s_yh    = sm + OFF_YH;
    float* s_yprev = sm + OFF_YPREV;

    const int tid  = threadIdx.x;
    const int lane = tid & 31;
    const int wrp  = tid >> 5;
    const int la   = lane;
    const int gt   = tid - 256;         // gemm-warp thread id (warps 8-15)
    const int op4  = tid & 255;         // Wih-phase o-pair
    const int kh4  = tid >> 8;          // Wih-phase k-half
    const int gU   = tid >> 6;          // update: batch row
    const int i2   = (tid & 63) * 2;    // update: unit pair
    const int gg   = tid >> 7;          // proj-phase warpgroup
    const int wt   = tid & 127;
    const int g0p  = gg * 2, g1p = g0p + 1;
    const int glp  = g0p + (wt >> 6);
    const int a63  = tid & 63;
    const int WB   = 1 + gg;

    const float ve_b_r = ve_b[0];

    // ---------- preload (encoder) ----------
    for (int i = tid; i < 256 * 64; i += NTHR) {
        int k = i >> 6, a = i & 63;
        sWk[i] = We_w[a * 257 + k];       // k-major [256k][64a]
    }
    if (tid < 512) s_bias[tid] = enc_bih[tid] + enc_bhh[tid];
    if (tid < 64) {
        s_Web[tid] = We_b[tid];
        ((float2*)s_wv)[tid] = make_float2(We_w[tid * 257 + 256], ve_w[tid]);
    }
    if (tid < GN * Tt) s_yh[tid] = y_hist[b0 * Tt + tid];
    for (int i = tid; i < 1024; i += NTHR) { s_h[i] = 0.f; s_c[i] = 0.f; }
    for (int i = tid; i < 2048; i += NTHR) { s_hd[i] = 0.f; s_cd[i] = 0.f; }
    __syncthreads();

    const ull* WihP  = reinterpret_cast<const ull*>(g_WihT);   // [k][256 o-pairs]
    const ull* WhhP  = reinterpret_cast<const ull*>(g_WhhT);
    const ull* WhhPd = reinterpret_cast<const ull*>(g_WhhTd);

    // ================= ENCODER: 64 steps =================
    for (int t = 0; t < Tt; ++t) {
        if (wrp < GN) {
            const int r = wrp;   // batch row (for E3/E4)
            // ---- E2 cooperative: warp covers k-pair chunk, all GN rows ----
            {
                const ull* Wk = (const ull*)sWk;   // [256 k][32 ull]
                const int kps = wrp * KPC;
                const int kpe = (wrp == GN - 1) ? 64 : kps + KPC;
                ull acc[GN];
                #pragma unroll
                for (int g = 0; g < GN; ++g) acc[g] = 0ULL;
                for (int kp = kps; kp < kpe; ++kp) {
                    ull wh0 = Wk[(2 * kp) * 32 + la];
                    ull wh1 = Wk[(2 * kp + 1) * 32 + la];
                    ull wc0 = Wk[(128 + 2 * kp) * 32 + la];
                    ull wc1 = Wk[(129 + 2 * kp) * 32 + la];
                    #pragma unroll
                    for (int g = 0; g < GN; ++g) {
                        ulonglong2 hp = *(const ulonglong2*)(s_hd + g * 256 + 4 * kp);
                        ulonglong2 cp = *(const ulonglong2*)(s_cd + g * 256 + 4 * kp);
                        ffma2(acc[g], wh0, hp.x);
                        ffma2(acc[g], wh1, hp.y);
                        ffma2(acc[g], wc0, cp.x);
                        ffma2(acc[g], wc1, cp.y);
                    }
                }
                #pragma unroll
                for (int g = 0; g < GN; ++g) {
                    float2 r2 = unpack2(acc[g]);
                    *(float2*)(s_ep + (wrp * GN + g) * 64 + 2 * la) = r2;
                }
            }
            bar8(GN * 32);
            // ---- sum partials -> base ----
            {
                const int tt2 = (wrp * 32 + la) * 2;
                #pragma unroll
                for (int j = 0; j < 2; ++j) {
                    int idx = tt2 + j;
                    int g = idx >> 6, a = idx & 63;
                    float ssum = s_Web[a];
                    #pragma unroll
                    for (int w2 = 0; w2 < GN; ++w2) ssum += s_ep[(w2 * GN + g) * 64 + a];
                    s_base[g * 64 + a] = ssum;
                }
            }
            bar8(GN * 32);
            // ---- E3+E4: scores + softmax (warp) + x_tilde ----
            {
                const float* Xg = X + ((size_t)(b0 + r) * Tt + t) * Dd;
                float xv0 = Xg[la], xv1 = Xg[la + 32], xv2 = Xg[la + 64], xv3 = Xg[la + 96];
                float s0 = ve_b_r, s1 = ve_b_r, s2 = ve_b_r, s3 = ve_b_r;
                const float* bg = s_base + r * 64;
                const float2* wv = (const float2*)s_wv;
                #pragma unroll 8
                for (int a = 0; a < 64; ++a) {
                    float ba = bg[a];
                    float2 w = wv[a];   // (w_feat, ve_w)
                    s0 = fmaf(w.y, tanh_fast(fmaf(xv0, w.x, ba)), s0);
                    s1 = fmaf(w.y, tanh_fast(fmaf(xv1, w.x, ba)), s1);
                    s2 = fmaf(w.y, tanh_fast(fmaf(xv2, w.x, ba)), s2);
                    s3 = fmaf(w.y, tanh_fast(fmaf(xv3, w.x, ba)), s3);
                }
                float m = fmaxf(fmaxf(s0, s1), fmaxf(s2, s3));
                #pragma unroll
                for (int o = 16; o; o >>= 1) m = fmaxf(m, __shfl_xor_sync(0xffffffffu, m, o));
                float e0 = __expf(s0 - m), e1 = __expf(s1 - m);
                float e2 = __expf(s2 - m), e3 = __expf(s3 - m);
                float ss = (e0 + e1) + (e2 + e3);
                #pragma unroll
                for (int o = 16; o; o >>= 1) ss += __shfl_xor_sync(0xffffffffu, ss, o);
                float inv = 1.f / ss;
                float v0 = xv0 * e0 * inv, v1 = xv1 * e1 * inv;
                float v2 = xv2 * e2 * inv, v3 = xv3 * e3 * inv;
                float* xd = s_xd + r * 256;
                *(float2*)(xd + 2 * la)        = make_float2(v0, v0);
                *(float2*)(xd + 2 * la + 64)   = make_float2(v1, v1);
                *(float2*)(xd + 2 * la + 128)  = make_float2(v2, v2);
                *(float2*)(xd + 2 * la + 192)  = make_float2(v3, v3);
            }
        } else if (wrp >= 8) {
            // ---- Whh · h -> s_gB (full k=128), 256 threads, op = gt ----
            ull acc[GN];
            #pragma unroll
            for (int g = 0; g < GN; ++g) acc[g] = 0ULL;
            #pragma unroll 2
            for (int kp = 0; kp < 64; ++kp) {
                ull w0 = WhhP[(2 * kp) * 256 + gt];
                ull w1 = WhhP[(2 * kp + 1) * 256 + gt];
                #pragma unroll
                for (int g = 0; g < GN; ++g) {
                    ulonglong2 hp = *(const ulonglong2*)(s_hd + g * 256 + 4 * kp);
                    ffma2(acc[g], w0, hp.x);
                    ffma2(acc[g], w1, hp.y);
                }
            }
            #pragma unroll
            for (int g = 0; g < GN; ++g) {
                float2 r2 = unpack2(acc[g]);
                *(float2*)(s_gB + g * 512 + 2 * gt) = r2;
            }
        }
        __syncthreads();
        // ---- phase4: Wih · x_tilde, (op4, kh4) split ----
        {
            float* dst = kh4 ? s_gC : s_gA;
            const int kb = kh4 * 64;
            ull acc[GN];
            #pragma unroll
            for (int g = 0; g < GN; ++g) acc[g] = 0ULL;
            #pragma unroll 2
            for (int kp = 0; kp < 32; ++kp) {
                int k = kb + 2 * kp;
                ull w0 = WihP[k * 256 + op4];
                ull w1 = WihP[(k + 1) * 256 + op4];
                #pragma unroll
                for (int g = 0; g < GN; ++g) {
                    ulonglong2 xp = *(const ulonglong2*)(s_xd + g * 256 + 2 * k);
                    ffma2(acc[g], w0, xp.x);
                    ffma2(acc[g], w1, xp.y);
                }
            }
            #pragma unroll
            for (int g = 0; g < GN; ++g) {
                float2 r2 = unpack2(acc[g]);
                *(float2*)(dst + g * 512 + 2 * op4) = r2;
            }
        }
        __syncthreads();
        // ---- E6: LSTM update, 2 units per thread ----
        if (gU < GN) {
            const float2* gA2 = (const float2*)(s_gA + gU * 512);
            const float2* gB2 = (const float2*)(s_gB + gU * 512);
            const float2* gC2 = (const float2*)(s_gC + gU * 512);
            const float2* b2  = (const float2*)s_bias;
            const int h2i = i2 >> 1;
            float pre[4][2];
            #pragma unroll
            for (int q = 0; q < 4; ++q) {
                int idx = q * 64 + h2i;
                float2 vA = gA2[idx], vB = gB2[idx], vC = gC2[idx], vb = b2[idx];
                pre[q][0] = ((vA.x + vB.x) + (vC.x + vb.x));
                pre[q][1] = ((vA.y + vB.y) + (vC.y + vb.y));
            }
            float hh[2], cc[2];
            #pragma unroll
            for (int j = 0; j < 2; ++j) {
                float ig = sigm(pre[0][j]);
                float fg = sigm(pre[1][j]);
                float gv = tanh_acc(pre[2][j]);
                float og = sigm(pre[3][j]);
                cc[j] = fmaf(fg, s_c[gU * 128 + i2 + j], ig * gv);
                hh[j] = og * tanh_acc(cc[j]);
                s_c[gU * 128 + i2 + j] = cc[j];
                s_h[gU * 128 + i2 + j] = hh[j];
            }
            *(float4*)(s_hd + gU * 256 + 2 * i2) = make_float4(hh[0], hh[0], hh[1], hh[1]);
            *(float4*)(s_cd + gU * 256 + 2 * i2) = make_float4(cc[0], cc[0], cc[1], cc[1]);
            *(float2*)(g_hid + ((size_t)(b0 + gU) * Tt + t) * Hh + i2) = make_float2(hh[0], hh[1]);
        }
        __syncthreads();
    }

    // ================= enc_proj (k-major weights in sWk) =================
    for (int i = tid; i < 128 * 64; i += NTHR) {
        int k = i >> 6, a = i & 63;
        sWk[i] = Wd_w[a * 384 + k];
    }
    __syncthreads();
    for (int t = 0; t < Tt; ++t) {
        if (g0p < GN) s_x[g0p * 128 + wt] = g_hid[((size_t)(b0 + g0p) * Tt + t) * Hh + wt];
        if (g1p < GN) s_x[g1p * 128 + wt] = g_hid[((size_t)(b0 + g1p) * Tt + t) * Hh + wt];
        barw(WB);
        if (glp < GN) {
            const float* hb = s_x + glp * 128;
            float aA = 0.f, aB = 0.f;
            #pragma unroll 8
            for (int k = 0; k < 128; k += 2) {
                aA = fmaf(hb[k],     sWk[k * 64 + a63], aA);
                aB = fmaf(hb[k + 1], sWk[(k + 1) * 64 + a63], aB);
            }
            g_proj[((size_t)(b0 + glp)) * ATT * Tt + a63 * Tt + t] = aA + aB;
        }
        barw(WB);
    }

    // ---------- preload (decoder) ----------
    __syncthreads();
    for (int i = tid; i < 256 * 64; i += NTHR) {
        int k = i >> 6, a = i & 63;
        sWk[i] = Wd_w[a * 384 + 128 + k];   // [d-part; c-part] k-major
    }
    if (tid < 512) {
        s_bias[tid] = dec_bih[tid] + dec_bhh[tid];
        s_dWih[tid] = dec_Wih[tid];
    }
    if (tid < 64) { s_Wdb[tid] = Wd_b[tid]; s_vdw[tid] = vd_w[tid]; }
    if (tid < 320) s_fcw[tid] = fc_w[tid];
    for (int i = tid; i < 1024; i += NTHR) { s_h[i] = 0.f; s_c[i] = 0.f; }
    for (int i = tid; i < 2048; i += NTHR) { s_hd[i] = 0.f; s_cd[i] = 0.f; }
    if (tid < GN) s_yprev[tid] = s_yh[tid * Tt + Tt - 1];
    const float vd_b_r = vd_b[0];
    const float fc_b_r = fc_b[0];
    __syncthreads();

    // D7 helper
    auto do_D7 = [&](int s) {
        const int r = wrp;
        float acc = 0.f;
        #pragma unroll
        for (int it = 0; it < 10; ++it) {
            int idx = lane + it * 32;
            float v;
            if (idx < 128)      v = s_h[r * 128 + idx];
            else if (idx < 256) v = s_x[r * 128 + idx - 128];
            else                v = s_yh[r * 64 + idx - 256];
            acc = fmaf(s_fcw[idx], v, acc);
        }
        #pragma unroll
        for (int o = 16; o; o >>= 1) acc += __shfl_xor_sync(0xffffffffu, acc, o);
        if (lane == 0) {
            float ov = acc + fc_b_r;
            s_yprev[r] = ov;
            out[(b0 + r) * HOR + s] = ov;
        }
    };

    // ================= DECODER: 24 steps =================
    for (int s = 0; s < HOR; ++s) {
        if (wrp < GN) {
            const int r = wrp;
            if (s > 0) do_D7(s - 1);
            // ---- D1 cooperative: warp covers k-pair chunk, all GN rows ----
            {
                const ull* Wk = (const ull*)sWk;
                const int kps = wrp * KPC;
                const int kpe = (wrp == GN - 1) ? 64 : kps + KPC;
                ull acc[GN];
                #pragma unroll
                for (int g = 0; g < GN; ++g) acc[g] = 0ULL;
                for (int kp = kps; kp < kpe; ++kp) {
                    ull wd0 = Wk[(2 * kp) * 32 + la];
                    ull wd1 = Wk[(2 * kp + 1) * 32 + la];
                    ull wc0 = Wk[(128 + 2 * kp) * 32 + la];
                    ull wc1 = Wk[(129 + 2 * kp) * 32 + la];
                    #pragma unroll
                    for (int g = 0; g < GN; ++g) {
                        ulonglong2 dp = *(const ulonglong2*)(s_hd + g * 256 + 4 * kp);
                        ulonglong2 cp = *(const ulonglong2*)(s_cd + g * 256 + 4 * kp);
                        ffma2(acc[g], wd0, dp.x);
                        ffma2(acc[g], wd1, dp.y);
                        ffma2(acc[g], wc0, cp.x);
                        ffma2(acc[g], wc1, cp.y);
                    }
                }
                #pragma unroll
                for (int g = 0; g < GN; ++g) {
                    float2 r2 = unpack2(acc[g]);
                    *(float2*)(s_ep + (wrp * GN + g) * 64 + 2 * la) = r2;
                }
            }
            bar8(GN * 32);
            // ---- sum partials -> base ----
            {
                const int tt2 = (wrp * 32 + la) * 2;
                #pragma unroll
                for (int j = 0; j < 2; ++j) {
                    int idx = tt2 + j;
                    int g = idx >> 6, a = idx & 63;
                    float ssum = s_Wdb[a];
                    #pragma unroll
                    for (int w2 = 0; w2 < GN; ++w2) ssum += s_ep[(w2 * GN + g) * 64 + a];
                    s_base[g * 64 + a] = ssum;
                }
            }
            bar8(GN * 32);
            // ---- D2+D3: temporal scores + softmax (warp) -> beta ----
            {
                const float* pp = g_proj + ((size_t)(b0 + r)) * ATT * Tt;
                const float* bg = s_base + r * 64;
                float ac0 = vd_b_r, ac1 = vd_b_r;
                #pragma unroll 4
                for (int a = 0; a < 64; ++a) {
                    float dca = bg[a];
                    float vw = s_vdw[a];
                    float p0 = pp[a * 64 + la];
                    float p1 = pp[a * 64 + la + 32];
                    ac0 = fmaf(vw, tanh_fast(p0 + dca), ac0);
                    ac1 = fmaf(vw, tanh_fast(p1 + dca), ac1);
                }
                float m = fmaxf(ac0, ac1);
                #pragma unroll
                for (int o = 16; o; o >>= 1) m = fmaxf(m, __shfl_xor_sync(0xffffffffu, m, o));
                float e0 = __expf(ac0 - m), e1 = __expf(ac1 - m);
                float ss = e0 + e1;
                #pragma unroll
                for (int o = 16; o; o >>= 1) ss += __shfl_xor_sync(0xffffffffu, ss, o);
                float inv = 1.f / ss;
                s_sc[r * 64 + la]      = e0 * inv;
                s_sc[r * 64 + la + 32] = e1 * inv;
            }
            __syncwarp();
            // ---- D4: context -> s_x (4 units per lane, float4) ----
            {
                const int u4 = 4 * la;
                const float4* hp4 = (const float4*)(g_hid + ((size_t)(b0 + r) * Tt) * Hh + u4);
                const float* be = s_sc + r * 64;
                float4 acc = make_float4(0.f, 0.f, 0.f, 0.f);
                #pragma unroll 4
                for (int tt = 0; tt < 64; ++tt) {
                    float b = be[tt];
                    float4 hv = hp4[tt * 32];
                    acc.x = fmaf(b, hv.x, acc.x);
                    acc.y = fmaf(b, hv.y, acc.y);
                    acc.z = fmaf(b, hv.z, acc.z);
                    acc.w = fmaf(b, hv.w, acc.w);
                }
                *(float4*)(s_x + r * 128 + u4) = acc;
            }
        } else if (wrp >= 8) {
            // ---- D5: Whh_dec · h -> s_gB (full k=128) ----
            ull acc[GN];
            #pragma unroll
            for (int g = 0; g < GN; ++g) acc[g] = 0ULL;
            #pragma unroll 2
            for (int kp = 0; kp < 64; ++kp) {
                ull w0 = WhhPd[(2 * kp) * 256 + gt];
                ull w1 = WhhPd[(2 * kp + 1) * 256 + gt];
                #pragma unroll
                for (int g = 0; g < GN; ++g) {
                    ulonglong2 hp = *(const ulonglong2*)(s_hd + g * 256 + 4 * kp);
                    ffma2(acc[g], w0, hp.x);
                    ffma2(acc[g], w1, hp.y);
                }
            }
            #pragma unroll
            for (int g = 0; g < GN; ++g) {
                float2 r2 = unpack2(acc[g]);
                *(float2*)(s_gB + g * 512 + 2 * gt) = r2;
            }
        }
        __syncthreads();
        // ---- D6: LSTM update (gB + bias + dWih*y_prev) ----
        if (gU < GN) {
            const float2* gB2 = (const float2*)(s_gB + gU * 512);
            const float2* b2  = (const float2*)s_bias;
            const float2* w2p = (const float2*)s_dWih;
            const int h2i = i2 >> 1;
            float y = s_yprev[gU];
            float pre[4][2];
            #pragma unroll
            for (int q = 0; q < 4; ++q) {
                int idx = q * 64 + h2i;
                float2 vB = gB2[idx], vb = b2[idx], vw = w2p[idx];
                pre[q][0] = fmaf(vw.x, y, vB.x + vb.x);
                pre[q][1] = fmaf(vw.y, y, vB.y + vb.y);
            }
            float hh[2], cc[2];
            #pragma unroll
            for (int j = 0; j < 2; ++j) {
                float ig = sigm(pre[0][j]);
                float fg = sigm(pre[1][j]);
                float gv = tanh_acc(pre[2][j]);
                float og = sigm(pre[3][j]);
                cc[j] = fmaf(fg, s_c[gU * 128 + i2 + j], ig * gv);
                hh[j] = og * tanh_acc(cc[j]);
                s_c[gU * 128 + i2 + j] = cc[j];
                s_h[gU * 128 + i2 + j] = hh[j];
            }
            *(float4*)(s_hd + gU * 256 + 2 * i2) = make_float4(hh[0], hh[0], hh[1], hh[1]);
            *(float4*)(s_cd + gU * 256 + 2 * i2) = make_float4(cc[0], cc[0], cc[1], cc[1]);
        }
        __syncthreads();
    }
    // final output step
    if (wrp < GN) do_D7(HOR - 1);
}

__global__ void __launch_bounds__(NTHR, 1)
darnn_kernel(const float* __restrict__ X,        const float* __restrict__ y_hist,
             const float* __restrict__ We_w,     const float* __restrict__ We_b,
             const float* __restrict__ ve_w,     const float* __restrict__ ve_b,
             const float* __restrict__ enc_bih,  const float* __restrict__ enc_bhh,
             const float* __restrict__ dec_Wih,  const float* __restrict__ dec_bih,
             const float* __restrict__ dec_bhh,
             const float* __restrict__ Wd_w,     const float* __restrict__ Wd_b,
             const float* __restrict__ vd_w,     const float* __restrict__ vd_b,
             const float* __restrict__ fc_w,     const float* __restrict__ fc_b,
             float* __restrict__ out) {
    extern __shared__ float sm[];
    if (blockIdx.x < NC7) {
        darnn_body<7>(blockIdx.x * 7,
                      X, y_hist, We_w, We_b, ve_w, ve_b, enc_bih, enc_bhh,
                      dec_Wih, dec_bih, dec_bhh, Wd_w, Wd_b, vd_w, vd_b,
                      fc_w, fc_b, out, sm);
    } else {
        darnn_body<6>(NC7 * 7 + (blockIdx.x - NC7) * 6,
                      X, y_hist, We_w, We_b, ve_w, ve_b, enc_bih, enc_bhh,
                      dec_Wih, dec_bih, dec_bhh, Wd_w, Wd_b, vd_w, vd_b,
                      fc_w, fc_b, out, sm);
    }
}

extern "C" void kernel_launch(void* const* d_in, const int* in_sizes, int n_in,
                              void* d_out, int out_size) {
    const float* X        = (const float*)d_in[0];
    const float* y_hist   = (const float*)d_in[1];
    const float* We_w     = (const float*)d_in[2];
    const float* We_b     = (const float*)d_in[3];
    const float* ve_w     = (const float*)d_in[4];
    const float* ve_b     = (const float*)d_in[5];
    const float* enc_Wih  = (const float*)d_in[6];
    const float* enc_Whh  = (const float*)d_in[7];
    const float* enc_bih  = (const float*)d_in[8];
    const float* enc_bhh  = (const float*)d_in[9];
    const float* dec_Wih  = (const float*)d_in[10];
    const float* dec_Whh  = (const float*)d_in[11];
    const float* dec_bih  = (const float*)d_in[12];
    const float* dec_bhh  = (const float*)d_in[13];
    const float* Wd_w     = (const float*)d_in[14];
    const float* Wd_b     = (const float*)d_in[15];
    const float* vd_w     = (const float*)d_in[16];
    const float* vd_b     = (const float*)d_in[17];
    const float* fc_w     = (const float*)d_in[18];
    const float* fc_b     = (const float*)d_in[19];
    float* out = (float*)d_out;

    cudaFuncSetAttribute(darnn_kernel,
                         cudaFuncAttributeMaxDynamicSharedMemorySize, SMEM_BYTES);

    transpose_k<<<(512 * 128 + 255) / 256, 256>>>(enc_Wih, enc_Whh, dec_Whh);
    darnn_kernel<<<NCTAS, NTHR, SMEM_BYTES>>>(
        X, y_hist, We_w, We_b, ve_w, ve_b,
        enc_bih, enc_bhh, dec_Wih, dec_bih, dec_bhh,
        Wd_w, Wd_b, vd_w, vd_b, fc_w, fc_b, out);
}

// round 16
// speedup vs baseline: 1.0692x; 1.0633x over previous
#include <cuda_runtime.h>
#include <cstdint>

typedef unsigned long long ull;

#define Bsz 1024
#define Tt 64
#define Dd 128
#define Hh 128
#define ATT 64
#define HOR 24
#define NTHR 512
#define NC7 136          // CTAs with 7 rows
#define NCTAS 148        // 136*7 + 12*6 = 1024

// ---------------- device scratch ----------------
__device__ float g_WihT[Dd * 4 * Hh];   // [k][512o]
__device__ float g_WhhT[Hh * 4 * Hh];   // [k][512o]
__device__ float g_WhhTd[Hh * 4 * Hh];  // [k][512o]
__device__ float g_hid[(size_t)Bsz * Tt * Hh];   // [b][t][h]
__device__ float g_proj[(size_t)Bsz * ATT * Tt]; // [b][a][t]

// ---------------- helpers ----------------
__device__ __forceinline__ float tanh_fast(float x) {
    float y; asm("tanh.approx.f32 %0, %1;" : "=f"(y) : "f"(x)); return y;
}
// sigmoid via single MUFU.TANH: sigma(x) = 0.5*tanh(x/2) + 0.5
__device__ __forceinline__ float sigm(float x) {
    return fmaf(0.5f, tanh_fast(0.5f * x), 0.5f);
}
// cell tanh via single MUFU.TANH (empirically ~fp32-accurate for our range)
__device__ __forceinline__ float tanh_acc(float x) {
    return tanh_fast(x);
}
__device__ __forceinline__ ull pack2(float lo, float hi) {
    ull r; asm("mov.b64 %0, {%1,%2};" : "=l"(r) : "f"(lo), "f"(hi)); return r;
}
__device__ __forceinline__ float2 unpack2(ull v) {
    float2 r; asm("mov.b64 {%0,%1}, %2;" : "=f"(r.x), "=f"(r.y) : "l"(v)); return r;
}
__device__ __forceinline__ void ffma2(ull &d, ull a, ull b) {
    asm("fma.rn.f32x2 %0, %1, %2, %0;" : "+l"(d) : "l"(a), "l"(b));
}
__device__ __forceinline__ void barw(int id) {  // warpgroup barrier (128 thr)
    asm volatile("bar.sync %0, 128;" :: "r"(id) : "memory");
}

// ---------------- prologue: transpose LSTM weights ----------------
__global__ void transpose_k(const float* __restrict__ Wih,
                            const float* __restrict__ Whh,
                            const float* __restrict__ Wdh) {
    int i = blockIdx.x * blockDim.x + threadIdx.x;
    if (i < 512 * 128) {
        int o = i >> 7, k = i & 127;
        g_WihT[k * 512 + o]  = Wih[i];
        g_WhhT[k * 512 + o]  = Whh[i];
        g_WhhTd[k * 512 + o] = Wdh[i];
    }
}

// smem float offsets (all multiples of 4)
#define OFF_W      0
#define SZ_W       24704              // 64*386 (enc stride 258, dec 386)
#define OFF_H      (OFF_W + SZ_W)
#define OFF_C      (OFF_H + 1024)
#define OFF_X      (OFF_C + 1024)     // context / proj staging
#define OFF_XD     (OFF_X + 1024)     // x_tilde duplicated [g][2k]
#define OFF_HD     (OFF_XD + 2048)    // h duplicated [g][2k]
#define OFF_BASE   (OFF_HD + 2048)
#define OFF_SC     (OFF_BASE + 512)
#define OFF_GA     (OFF_SC + 512)     // Wih partial kh=0
#define OFF_GB     (OFF_GA + 4096)    // Whh full
#define OFF_GC     (OFF_GB + 4096)    // Wih partial kh=1
#define OFF_BIAS   (OFF_GC + 4096)
#define OFF_WEB    (OFF_BIAS + 512)
#define OFF_WV     (OFF_WEB + 64)     // (w_feat, ve_w) pairs, 128 floats
#define OFF_WDB    (OFF_WV + 128)
#define OFF_VDW    (OFF_WDB + 64)
#define OFF_DWIH   (OFF_VDW + 64)
#define OFF_FCW    (OFF_DWIH + 512)
#define OFF_YH     (OFF_FCW + 320)
#define OFF_YPREV  (OFF_YH + 512)
#define SMEM_FLOATS (OFF_YPREV + 8)
#define SMEM_BYTES  (SMEM_FLOATS * 4)

template<int GN>
__device__ __forceinline__ void darnn_body(
    const int b0,
    const float* __restrict__ X,        const float* __restrict__ y_hist,
    const float* __restrict__ We_w,     const float* __restrict__ We_b,
    const float* __restrict__ ve_w,     const float* __restrict__ ve_b,
    const float* __restrict__ enc_bih,  const float* __restrict__ enc_bhh,
    const float* __restrict__ dec_Wih,  const float* __restrict__ dec_bih,
    const float* __restrict__ dec_bhh,
    const float* __restrict__ Wd_w,     const float* __restrict__ Wd_b,
    const float* __restrict__ vd_w,     const float* __restrict__ vd_b,
    const float* __restrict__ fc_w,     const float* __restrict__ fc_b,
    float* __restrict__ out, float* sm)
{
    float* sW      = sm + OFF_W;
    float* s_h     = sm + OFF_H;
    float* s_c     = sm + OFF_C;
    float* s_x     = sm + OFF_X;
    float* s_xd    = sm + OFF_XD;
    float* s_hd    = sm + OFF_HD;
    float* s_base  = sm + OFF_BASE;
    float* s_sc    = sm + OFF_SC;
    float* s_gA    = sm + OFF_GA;
    float* s_gB    = sm + OFF_GB;
    float* s_gC    = sm + OFF_GC;
    float* s_bias  = sm + OFF_BIAS;
    float* s_Web   = sm + OFF_WEB;
    float* s_wv    = sm + OFF_WV;
    float* s_Wdb   = sm + OFF_WDB;
    float* s_vdw   = sm + OFF_VDW;
    float* s_dWih  = sm + OFF_DWIH;
    float* s_fcw   = sm + OFF_FCW;
    float* s_yh    = sm + OFF_YH;
    float* s_yprev = sm + OFF_YPREV;

    const int tid  = threadIdx.x;
    const int lane = tid & 31;
    const int wrp  = tid >> 5;
    const int la   = lane;
    const int gt   = tid - 256;         // gemm-warp thread id (warps 8-15)
    const int op4  = tid & 255;         // Wih-phase o-pair
    const int kh4  = tid >> 8;          // Wih-phase k-half
    const int gU   = tid >> 6;          // update: batch row
    const int i2   = (tid & 63) * 2;    // update: unit pair
    const int gg   = tid >> 7;          // proj-phase warpgroup
    const int wt   = tid & 127;
    const int g0p  = gg * 2, g1p = g0p + 1;
    const int glp  = g0p + (wt >> 6);
    const int a63  = tid & 63;
    const int WB   = 1 + gg;

    const float ve_b_r = ve_b[0];

    // ---------- preload (encoder) ----------
    for (int i = tid; i < 64 * 257; i += NTHR) {
        int r = i / 257, c = i - r * 257;
        sW[r * 258 + c] = We_w[i];
    }
    if (tid < 512) s_bias[tid] = enc_bih[tid] + enc_bhh[tid];
    if (tid < 64) {
        s_Web[tid] = We_b[tid];
        ((float2*)s_wv)[tid] = make_float2(We_w[tid * 257 + 256], ve_w[tid]);
    }
    if (tid < GN * Tt) s_yh[tid] = y_hist[b0 * Tt + tid];
    for (int i = tid; i < 1024; i += NTHR) { s_h[i] = 0.f; s_c[i] = 0.f; }
    for (int i = tid; i < 2048; i += NTHR) s_hd[i] = 0.f;
    __syncthreads();

    const ull* WihP  = reinterpret_cast<const ull*>(g_WihT);   // [k][256 o-pairs]
    const ull* WhhP  = reinterpret_cast<const ull*>(g_WhhT);
    const ull* WhhPd = reinterpret_cast<const ull*>(g_WhhTd);

    // ================= ENCODER: 64 steps =================
    for (int t = 0; t < Tt; ++t) {
        if (wrp < GN) {
            const int r = wrp;   // batch row
            // ---- E2: base[a] for a = la, la+32 ----
            {
                const ull* Wr0 = (const ull*)(sW + la * 258);
                const ull* Wr1 = (const ull*)(sW + (la + 32) * 258);
                const ull* hg2 = (const ull*)(s_h + r * 128);
                const ull* cg2 = (const ull*)(s_c + r * 128);
                ull a0A = pack2(s_Web[la], 0.f), a0B = 0ULL;
                ull a1A = pack2(s_Web[la + 32], 0.f), a1B = 0ULL;
                #pragma unroll 4
                for (int j = 0; j < 64; j += 2) {
                    ull h0 = hg2[j], h1 = hg2[j + 1];
                    ffma2(a0A, Wr0[j], h0); ffma2(a0B, Wr0[j + 1], h1);
                    ffma2(a1A, Wr1[j], h0); ffma2(a1B, Wr1[j + 1], h1);
                }
                #pragma unroll 4
                for (int j = 0; j < 64; j += 2) {
                    ull c0 = cg2[j], c1 = cg2[j + 1];
                    ffma2(a0A, Wr0[64 + j], c0); ffma2(a0B, Wr0[64 + j + 1], c1);
                    ffma2(a1A, Wr1[64 + j], c0); ffma2(a1B, Wr1[64 + j + 1], c1);
                }
                float2 p = unpack2(a0A), q = unpack2(a0B);
                s_base[r * 64 + la] = (p.x + q.x) + (p.y + q.y);
                p = unpack2(a1A); q = unpack2(a1B);
                s_base[r * 64 + la + 32] = (p.x + q.x) + (p.y + q.y);
            }
            __syncwarp();
            // ---- E3+E4: scores + softmax (warp) + x_tilde ----
            {
                const float* Xg = X + ((size_t)(b0 + r) * Tt + t) * Dd;
                float xv0 = Xg[la], xv1 = Xg[la + 32], xv2 = Xg[la + 64], xv3 = Xg[la + 96];
                float s0 = ve_b_r, s1 = ve_b_r, s2 = ve_b_r, s3 = ve_b_r;
                const float* bg = s_base + r * 64;
                const float2* wv = (const float2*)s_wv;
                #pragma unroll 8
                for (int a = 0; a < 64; ++a) {
                    float ba = bg[a];
                    float2 w = wv[a];   // (w_feat, ve_w)
                    s0 = fmaf(w.y, tanh_fast(fmaf(xv0, w.x, ba)), s0);
                    s1 = fmaf(w.y, tanh_fast(fmaf(xv1, w.x, ba)), s1);
                    s2 = fmaf(w.y, tanh_fast(fmaf(xv2, w.x, ba)), s2);
                    s3 = fmaf(w.y, tanh_fast(fmaf(xv3, w.x, ba)), s3);
                }
                float m = fmaxf(fmaxf(s0, s1), fmaxf(s2, s3));
                #pragma unroll
                for (int o = 16; o; o >>= 1) m = fmaxf(m, __shfl_xor_sync(0xffffffffu, m, o));
                float e0 = __expf(s0 - m), e1 = __expf(s1 - m);
                float e2 = __expf(s2 - m), e3 = __expf(s3 - m);
                float ss = (e0 + e1) + (e2 + e3);
                #pragma unroll
                for (int o = 16; o; o >>= 1) ss += __shfl_xor_sync(0xffffffffu, ss, o);
                float inv = 1.f / ss;
                float v0 = xv0 * e0 * inv, v1 = xv1 * e1 * inv;
                float v2 = xv2 * e2 * inv, v3 = xv3 * e3 * inv;
                float* xd = s_xd + r * 256;
                *(float2*)(xd + 2 * la)        = make_float2(v0, v0);
                *(float2*)(xd + 2 * la + 64)   = make_float2(v1, v1);
                *(float2*)(xd + 2 * la + 128)  = make_float2(v2, v2);
                *(float2*)(xd + 2 * la + 192)  = make_float2(v3, v3);
            }
        } else if (wrp >= 8) {
            // ---- Whh · h -> s_gB (full k=128), 256 threads, op = gt ----
            ull acc[GN];
            #pragma unroll
            for (int g = 0; g < GN; ++g) acc[g] = 0ULL;
            #pragma unroll 2
            for (int kp = 0; kp < 64; ++kp) {
                ull w0 = WhhP[(2 * kp) * 256 + gt];
                ull w1 = WhhP[(2 * kp + 1) * 256 + gt];
                #pragma unroll
                for (int g = 0; g < GN; ++g) {
                    ulonglong2 hp = *(const ulonglong2*)(s_hd + g * 256 + 4 * kp);
                    ffma2(acc[g], w0, hp.x);
                    ffma2(acc[g], w1, hp.y);
                }
            }
            #pragma unroll
            for (int g = 0; g < GN; ++g) {
                float2 r2 = unpack2(acc[g]);
                *(float2*)(s_gB + g * 512 + 2 * gt) = r2;
            }
        }
        __syncthreads();
        // ---- phase4: Wih · x_tilde, (op4, kh4) split ----
        {
            float* dst = kh4 ? s_gC : s_gA;
            const int kb = kh4 * 64;
            ull acc[GN];
            #pragma unroll
            for (int g = 0; g < GN; ++g) acc[g] = 0ULL;
            #pragma unroll 2
            for (int kp = 0; kp < 32; ++kp) {
                int k = kb + 2 * kp;
                ull w0 = WihP[k * 256 + op4];
                ull w1 = WihP[(k + 1) * 256 + op4];
                #pragma unroll
                for (int g = 0; g < GN; ++g) {
                    ulonglong2 xp = *(const ulonglong2*)(s_xd + g * 256 + 2 * k);
                    ffma2(acc[g], w0, xp.x);
                    ffma2(acc[g], w1, xp.y);
                }
            }
            #pragma unroll
            for (int g = 0; g < GN; ++g) {
                float2 r2 = unpack2(acc[g]);
                *(float2*)(dst + g * 512 + 2 * op4) = r2;
            }
        }
        __syncthreads();
        // ---- E6: LSTM update, 2 units per thread (fast activations) ----
        if (gU < GN) {
            const float2* gA2 = (const float2*)(s_gA + gU * 512);
            const float2* gB2 = (const float2*)(s_gB + gU * 512);
            const float2* gC2 = (const float2*)(s_gC + gU * 512);
            const float2* b2  = (const float2*)s_bias;
            const int h2i = i2 >> 1;
            float pre[4][2];
            #pragma unroll
            for (int q = 0; q < 4; ++q) {
                int idx = q * 64 + h2i;
                float2 vA = gA2[idx], vB = gB2[idx], vC = gC2[idx], vb = b2[idx];
                pre[q][0] = ((vA.x + vB.x) + (vC.x + vb.x));
                pre[q][1] = ((vA.y + vB.y) + (vC.y + vb.y));
            }
            float hh[2];
            #pragma unroll
            for (int j = 0; j < 2; ++j) {
                float ig = sigm(pre[0][j]);
                float fg = sigm(pre[1][j]);
                float gv = tanh_acc(pre[2][j]);
                float og = sigm(pre[3][j]);
                float c2 = fmaf(fg, s_c[gU * 128 + i2 + j], ig * gv);
                float h2 = og * tanh_acc(c2);
                s_c[gU * 128 + i2 + j] = c2;
                s_h[gU * 128 + i2 + j] = h2;
                hh[j] = h2;
            }
            *(float4*)(s_hd + gU * 256 + 2 * i2) = make_float4(hh[0], hh[0], hh[1], hh[1]);
            *(float2*)(g_hid + ((size_t)(b0 + gU) * Tt + t) * Hh + i2) = make_float2(hh[0], hh[1]);
        }
        __syncthreads();
    }

    // ================= enc_proj =================
    for (int i = tid; i < 64 * 384; i += NTHR) {
        int r = i / 384, c = i - r * 384;
        sW[r * 386 + c] = Wd_w[i];
    }
    __syncthreads();
    for (int t = 0; t < Tt; ++t) {
        if (g0p < GN) s_x[g0p * 128 + wt] = g_hid[((size_t)(b0 + g0p) * Tt + t) * Hh + wt];
        if (g1p < GN) s_x[g1p * 128 + wt] = g_hid[((size_t)(b0 + g1p) * Tt + t) * Hh + wt];
        barw(WB);
        if (glp < GN) {
            const ull* Wr2 = (const ull*)(sW + a63 * 386);
            const ull* hg2 = (const ull*)(s_x + glp * 128);
            ull aA = 0ULL, aB = 0ULL;
            #pragma unroll 8
            for (int j = 0; j < 64; j += 2) {
                ffma2(aA, Wr2[j], hg2[j]);
                ffma2(aB, Wr2[j + 1], hg2[j + 1]);
            }
            float2 ra = unpack2(aA), rb = unpack2(aB);
            g_proj[((size_t)(b0 + glp)) * ATT * Tt + a63 * Tt + t] = (ra.x + rb.x) + (ra.y + rb.y);
        }
        barw(WB);
    }

    // ---------- preload (decoder) ----------
    __syncthreads();
    if (tid < 512) {
        s_bias[tid] = dec_bih[tid] + dec_bhh[tid];
        s_dWih[tid] = dec_Wih[tid];
    }
    if (tid < 64) { s_Wdb[tid] = Wd_b[tid]; s_vdw[tid] = vd_w[tid]; }
    if (tid < 320) s_fcw[tid] = fc_w[tid];
    for (int i = tid; i < 1024; i += NTHR) { s_h[i] = 0.f; s_c[i] = 0.f; }
    for (int i = tid; i < 2048; i += NTHR) s_hd[i] = 0.f;
    if (tid < GN) s_yprev[tid] = s_yh[tid * Tt + Tt - 1];
    const float vd_b_r = vd_b[0];
    const float fc_b_r = fc_b[0];
    __syncthreads();

    // D7 helper
    auto do_D7 = [&](int s) {
        const int r = wrp;
        float acc = 0.f;
        #pragma unroll
        for (int it = 0; it < 10; ++it) {
            int idx = lane + it * 32;
            float v;
            if (idx < 128)      v = s_h[r * 128 + idx];
            else if (idx < 256) v = s_x[r * 128 + idx - 128];
            else                v = s_yh[r * 64 + idx - 256];
            acc = fmaf(s_fcw[idx], v, acc);
        }
        #pragma unroll
        for (int o = 16; o; o >>= 1) acc += __shfl_xor_sync(0xffffffffu, acc, o);
        if (lane == 0) {
            float ov = acc + fc_b_r;
            s_yprev[r] = ov;
            out[(b0 + r) * HOR + s] = ov;
        }
    };

    // ================= DECODER: 24 steps =================
    for (int s = 0; s < HOR; ++s) {
        if (wrp < GN) {
            const int r = wrp;
            if (s > 0) do_D7(s - 1);
            // ---- D1: dc[a] for a = la, la+32 ----
            {
                const ull* W0d = (const ull*)(sW + la * 386 + 128);
                const ull* W0c = (const ull*)(sW + la * 386 + 256);
                const ull* W1d = (const ull*)(sW + (la + 32) * 386 + 128);
                const ull* W1c = (const ull*)(sW + (la + 32) * 386 + 256);
                const ull* dg2 = (const ull*)(s_h + r * 128);
                const ull* cg2 = (const ull*)(s_c + r * 128);
                ull a0A = pack2(s_Wdb[la], 0.f), a0B = 0ULL;
                ull a1A = pack2(s_Wdb[la + 32], 0.f), a1B = 0ULL;
                #pragma unroll 4
                for (int j = 0; j < 64; j += 2) {
                    ull d0 = dg2[j], d1 = dg2[j + 1];
                    ffma2(a0A, W0d[j], d0); ffma2(a0B, W0d[j + 1], d1);
                    ffma2(a1A, W1d[j], d0); ffma2(a1B, W1d[j + 1], d1);
                }
                #pragma unroll 4
                for (int j = 0; j < 64; j += 2) {
                    ull c0 = cg2[j], c1 = cg2[j + 1];
                    ffma2(a0A, W0c[j], c0); ffma2(a0B, W0c[j + 1], c1);
                    ffma2(a1A, W1c[j], c0); ffma2(a1B, W1c[j + 1], c1);
                }
                float2 p = unpack2(a0A), q = unpack2(a0B);
                s_base[r * 64 + la] = (p.x + q.x) + (p.y + q.y);
                p = unpack2(a1A); q = unpack2(a1B);
                s_base[r * 64 + la + 32] = (p.x + q.x) + (p.y + q.y);
            }
            __syncwarp();
            // ---- D2+D3: temporal scores + softmax (warp) -> beta ----
            {
                const float* pp = g_proj + ((size_t)(b0 + r)) * ATT * Tt;
                const float* bg = s_base + r * 64;
                float ac0 = vd_b_r, ac1 = vd_b_r;
                #pragma unroll 4
                for (int a = 0; a < 64; ++a) {
                    float dca = bg[a];
                    float vw = s_vdw[a];
                    float p0 = pp[a * 64 + la];
                    float p1 = pp[a * 64 + la + 32];
                    ac0 = fmaf(vw, tanh_fast(p0 + dca), ac0);
                    ac1 = fmaf(vw, tanh_fast(p1 + dca), ac1);
                }
                float m = fmaxf(ac0, ac1);
                #pragma unroll
                for (int o = 16; o; o >>= 1) m = fmaxf(m, __shfl_xor_sync(0xffffffffu, m, o));
                float e0 = __expf(ac0 - m), e1 = __expf(ac1 - m);
                float ss = e0 + e1;
                #pragma unroll
                for (int o = 16; o; o >>= 1) ss += __shfl_xor_sync(0xffffffffu, ss, o);
                float inv = 1.f / ss;
                s_sc[r * 64 + la]      = e0 * inv;
                s_sc[r * 64 + la + 32] = e1 * inv;
            }
            __syncwarp();
            // ---- D4: context -> s_x (4 units per lane, float4) ----
            {
                const int u4 = 4 * la;
                const float4* hp4 = (const float4*)(g_hid + ((size_t)(b0 + r) * Tt) * Hh + u4);
                const float* be = s_sc + r * 64;
                float4 acc = make_float4(0.f, 0.f, 0.f, 0.f);
                #pragma unroll 4
                for (int tt = 0; tt < 64; ++tt) {
                    float b = be[tt];
                    float4 hv = hp4[tt * 32];
                    acc.x = fmaf(b, hv.x, acc.x);
                    acc.y = fmaf(b, hv.y, acc.y);
                    acc.z = fmaf(b, hv.z, acc.z);
                    acc.w = fmaf(b, hv.w, acc.w);
                }
                *(float4*)(s_x + r * 128 + u4) = acc;
            }
        } else if (wrp >= 8) {
            // ---- D5: Whh_dec · h -> s_gB (full k=128) ----
            ull acc[GN];
            #pragma unroll
            for (int g = 0; g < GN; ++g) acc[g] = 0ULL;
            #pragma unroll 2
            for (int kp = 0; kp < 64; ++kp) {
                ull w0 = WhhPd[(2 * kp) * 256 + gt];
                ull w1 = WhhPd[(2 * kp + 1) * 256 + gt];
                #pragma unroll
                for (int g = 0; g < GN; ++g) {
                    ulonglong2 hp = *(const ulonglong2*)(s_hd + g * 256 + 4 * kp);
                    ffma2(acc[g], w0, hp.x);
                    ffma2(acc[g], w1, hp.y);
                }
            }
            #pragma unroll
            for (int g = 0; g < GN; ++g) {
                float2 r2 = unpack2(acc[g]);
                *(float2*)(s_gB + g * 512 + 2 * gt) = r2;
            }
        }
        __syncthreads();
        // ---- D6: LSTM update (gB + bias + dWih*y_prev), fast activations ----
        if (gU < GN) {
            const float2* gB2 = (const float2*)(s_gB + gU * 512);
            const float2* b2  = (const float2*)s_bias;
            const float2* w2p = (const float2*)s_dWih;
            const int h2i = i2 >> 1;
            float y = s_yprev[gU];
            float pre[4][2];
            #pragma unroll
            for (int q = 0; q < 4; ++q) {
                int idx = q * 64 + h2i;
                float2 vB = gB2[idx], vb = b2[idx], vw = w2p[idx];
                pre[q][0] = fmaf(vw.x, y, vB.x + vb.x);
                pre[q][1] = fmaf(vw.y, y, vB.y + vb.y);
            }
            float hh[2];
            #pragma unroll
            for (int j = 0; j < 2; ++j) {
                float ig = sigm(pre[0][j]);
                float fg = sigm(pre[1][j]);
                float gv = tanh_acc(pre[2][j]);
                float og = sigm(pre[3][j]);
                float c2 = fmaf(fg, s_c[gU * 128 + i2 + j], ig * gv);
                float h2 = og * tanh_acc(c2);
                s_c[gU * 128 + i2 + j] = c2;
                s_h[gU * 128 + i2 + j] = h2;
                hh[j] = h2;
            }
            *(float4*)(s_hd + gU * 256 + 2 * i2) = make_float4(hh[0], hh[0], hh[1], hh[1]);
        }
        __syncthreads();
    }
    // final output step
    if (wrp < GN) do_D7(HOR - 1);
}

__global__ void __launch_bounds__(NTHR, 1)
darnn_kernel(const float* __restrict__ X,        const float* __restrict__ y_hist,
             const float* __restrict__ We_w,     const float* __restrict__ We_b,
             const float* __restrict__ ve_w,     const float* __restrict__ ve_b,
             const float* __restrict__ enc_bih,  const float* __restrict__ enc_bhh,
             const float* __restrict__ dec_Wih,  const float* __restrict__ dec_bih,
             const float* __restrict__ dec_bhh,
             const float* __restrict__ Wd_w,     const float* __restrict__ Wd_b,
             const float* __restrict__ vd_w,     const float* __restrict__ vd_b,
             const float* __restrict__ fc_w,     const float* __restrict__ fc_b,
             float* __restrict__ out) {
    extern __shared__ float sm[];
    if (blockIdx.x < NC7) {
        darnn_body<7>(blockIdx.x * 7,
                      X, y_hist, We_w, We_b, ve_w, ve_b, enc_bih, enc_bhh,
                      dec_Wih, dec_bih, dec_bhh, Wd_w, Wd_b, vd_w, vd_b,
                      fc_w, fc_b, out, sm);
    } else {
        darnn_body<6>(NC7 * 7 + (blockIdx.x - NC7) * 6,
                      X, y_hist, We_w, We_b, ve_w, ve_b, enc_bih, enc_bhh,
                      dec_Wih, dec_bih, dec_bhh, Wd_w, Wd_b, vd_w, vd_b,
                      fc_w, fc_b, out, sm);
    }
}

extern "C" void kernel_launch(void* const* d_in, const int* in_sizes, int n_in,
                              void* d_out, int out_size) {
    const float* X        = (const float*)d_in[0];
    const float* y_hist   = (const float*)d_in[1];
    const float* We_w     = (const float*)d_in[2];
    const float* We_b     = (const float*)d_in[3];
    const float* ve_w     = (const float*)d_in[4];
    const float* ve_b     = (const float*)d_in[5];
    const float* enc_Wih  = (const float*)d_in[6];
    const float* enc_Whh  = (const float*)d_in[7];
    const float* enc_bih  = (const float*)d_in[8];
    const float* enc_bhh  = (const float*)d_in[9];
    const float* dec_Wih  = (const float*)d_in[10];
    const float* dec_Whh  = (const float*)d_in[11];
    const float* dec_bih  = (const float*)d_in[12];
    const float* dec_bhh  = (const float*)d_in[13];
    const float* Wd_w     = (const float*)d_in[14];
    const float* Wd_b     = (const float*)d_in[15];
    const float* vd_w     = (const float*)d_in[16];
    const float* vd_b     = (const float*)d_in[17];
    const float* fc_w     = (const float*)d_in[18];
    const float* fc_b     = (const float*)d_in[19];
    float* out = (float*)d_out;

    cudaFuncSetAttribute(darnn_kernel,
                         cudaFuncAttributeMaxDynamicSharedMemorySize, SMEM_BYTES);

    transpose_k<<<(512 * 128 + 255) / 256, 256>>>(enc_Wih, enc_Whh, dec_Whh);
    darnn_kernel<<<NCTAS, NTHR, SMEM_BYTES>>>(
        X, y_hist, We_w, We_b, ve_w, ve_b,
        enc_bih, enc_bhh, dec_Wih, dec_bih, dec_bhh,
        Wd_w, Wd_b, vd_w, vd_b, fc_w, fc_b, out);
}